// round 2
// baseline (speedup 1.0000x reference)
#include <cuda_runtime.h>
#include <math.h>

#define BB 2
#define TT 2048
#define EE 768
#define HH 12
#define DD 64
#define MM (BB*TT)      // 4096 tokens
#define FFN (4*EE)      // 3072

// ---- scratch (no allocs allowed; __device__ globals) ----
__device__ float g_h1 [MM*EE];
__device__ float g_q  [MM*EE];
__device__ float g_k  [MM*EE];
__device__ float g_v  [MM*EE];
__device__ float g_ctx[MM*EE];
__device__ float g_x1 [MM*EE];
__device__ float g_h2 [MM*EE];
__device__ float g_f1 [MM*FFN];

// ============================================================
// LayerNorm (var with ddof=1), one block per row, 256 threads
// ============================================================
__global__ __launch_bounds__(256) void ln_kernel(
    const float* __restrict__ x, const float* __restrict__ sc,
    const float* __restrict__ sh, float* __restrict__ out)
{
    int row = blockIdx.x;
    int t = threadIdx.x;
    const float* xr = x + (size_t)row * EE;
    float v0 = xr[t], v1 = xr[t + 256], v2 = xr[t + 512];
    float s  = v0 + v1 + v2;
    float ss = v0*v0 + v1*v1 + v2*v2;
    #pragma unroll
    for (int o = 16; o; o >>= 1) {
        s  += __shfl_xor_sync(0xffffffffu, s,  o);
        ss += __shfl_xor_sync(0xffffffffu, ss, o);
    }
    __shared__ float red[2][8];
    __shared__ float mean_s, rstd_s;
    int w = t >> 5, ln = t & 31;
    if (ln == 0) { red[0][w] = s; red[1][w] = ss; }
    __syncthreads();
    if (t == 0) {
        float S = 0.f, SS = 0.f;
        #pragma unroll
        for (int i = 0; i < 8; i++) { S += red[0][i]; SS += red[1][i]; }
        float mean = S / (float)EE;
        float var  = (SS - S * mean) / (float)(EE - 1);   // ddof=1
        mean_s = mean;
        rstd_s = rsqrtf(var + 1e-5f);
    }
    __syncthreads();
    float mean = mean_s, r = rstd_s;
    float* orow = out + (size_t)row * EE;
    orow[t]       = sc[t]       * (v0 - mean) * r + sh[t];
    orow[t + 256] = sc[t + 256] * (v1 - mean) * r + sh[t + 256];
    orow[t + 512] = sc[t + 512] * (v2 - mean) * r + sh[t + 512];
}

// ============================================================
// SGEMM: C[M,N] = A[M,K] @ B[K,N], row-major.
// 128x128 tile, K-tile 8, 256 threads, 8x8 per thread, prefetch.
// EPI: 0 = plain, 1 = +bias +resid, 2 = +bias then GELU
// ============================================================
template<int EPI>
__global__ __launch_bounds__(256) void sgemm_kernel(
    const float* __restrict__ A, const float* __restrict__ Bw,
    float* __restrict__ C, int M, int N, int K,
    const float* __restrict__ bias, const float* __restrict__ resid)
{
    __shared__ float As[8][128];
    __shared__ float Bs[8][132];
    int tid = threadIdx.x;
    int tx = tid & 15, ty = tid >> 4;
    int rowBase = blockIdx.y * 128, colBase = blockIdx.x * 128;
    int arow = tid >> 1, ak = (tid & 1) * 4;
    int brow = tid >> 5, bcol = (tid & 31) * 4;
    const float* Ap = A + (size_t)(rowBase + arow) * K + ak;
    const float* Bp = Bw + colBase + bcol;

    float4 av = *(const float4*)Ap;
    float4 bv = *(const float4*)(Bp + (size_t)brow * N);

    float acc[8][8];
    #pragma unroll
    for (int i = 0; i < 8; i++)
        #pragma unroll
        for (int j = 0; j < 8; j++) acc[i][j] = 0.f;

    for (int k0 = 0; k0 < K; k0 += 8) {
        __syncthreads();
        As[ak + 0][arow] = av.x;
        As[ak + 1][arow] = av.y;
        As[ak + 2][arow] = av.z;
        As[ak + 3][arow] = av.w;
        *(float4*)&Bs[brow][bcol] = bv;
        __syncthreads();
        if (k0 + 8 < K) {
            av = *(const float4*)(Ap + k0 + 8);
            bv = *(const float4*)(Bp + (size_t)(k0 + 8 + brow) * N);
        }
        #pragma unroll
        for (int kk = 0; kk < 8; kk++) {
            float4 a0 = *(const float4*)&As[kk][ty * 8];
            float4 a1 = *(const float4*)&As[kk][ty * 8 + 4];
            float4 b0 = *(const float4*)&Bs[kk][tx * 8];
            float4 b1 = *(const float4*)&Bs[kk][tx * 8 + 4];
            float ar[8] = {a0.x,a0.y,a0.z,a0.w,a1.x,a1.y,a1.z,a1.w};
            float br[8] = {b0.x,b0.y,b0.z,b0.w,b1.x,b1.y,b1.z,b1.w};
            #pragma unroll
            for (int i = 0; i < 8; i++)
                #pragma unroll
                for (int j = 0; j < 8; j++)
                    acc[i][j] += ar[i] * br[j];
        }
    }

    #pragma unroll
    for (int i = 0; i < 8; i++) {
        int r = rowBase + ty * 8 + i;
        #pragma unroll
        for (int j = 0; j < 8; j++) {
            int c = colBase + tx * 8 + j;
            float v = acc[i][j];
            if (EPI >= 1) v += bias[c];
            if (EPI == 2) {
                float u = v;
                v = 0.5f * u * (1.f + tanhf(0.7978845608028654f * (u + 0.044715f * u * u * u)));
            }
            if (EPI == 1) v += resid[(size_t)r * N + c];
            C[(size_t)r * N + c] = v;
        }
    }
}

// ============================================================
// Causal flash attention, fp32. One thread = one query row.
// BM=128 (threads), BN=32 key tile. Online softmax in log2 domain.
// Q staged transposed in smem (conflict-free compute reads),
// K/V tiles read as broadcast float4 (4 FMA per LDS).
// ============================================================
__global__ __launch_bounds__(128) void attn_kernel(
    const float* __restrict__ q, const float* __restrict__ k,
    const float* __restrict__ v, float* __restrict__ ctx)
{
    __shared__ float Qt[64][128];   // [d][row]
    __shared__ float Ks[32][64];
    __shared__ float Vs[32][64];

    int tid = threadIdx.x;
    int bh = blockIdx.y;
    int b = bh / HH, h = bh % HH;
    int q0 = blockIdx.x * 128;
    const float* qb = q + (size_t)b * TT * EE + h * DD;
    const float* kb = k + (size_t)b * TT * EE + h * DD;
    const float* vb = v + (size_t)b * TT * EE + h * DD;
    const float SC = 0.125f * 1.4426950408889634f;   // 1/sqrt(64) * log2(e)

    for (int i = tid; i < 128 * 64; i += 128) {
        int rr = i >> 6, dd = i & 63;
        Qt[dd][rr] = qb[(size_t)(q0 + rr) * EE + dd] * SC;
    }

    float O[64];
    #pragma unroll
    for (int d = 0; d < 64; d++) O[d] = 0.f;
    float m = -1e30f, l = 0.f;
    int qi = q0 + tid;
    int ktiles = q0 / 32 + 4;

    for (int jt = 0; jt < ktiles; ++jt) {
        int k0 = jt * 32;
        __syncthreads();
        for (int i = tid; i < 32 * 64; i += 128) {
            int rr = i >> 6, dd = i & 63;
            Ks[rr][dd] = kb[(size_t)(k0 + rr) * EE + dd];
            Vs[rr][dd] = vb[(size_t)(k0 + rr) * EE + dd];
        }
        __syncthreads();

        float s[32];
        #pragma unroll
        for (int c = 0; c < 32; c++) s[c] = 0.f;
        #pragma unroll
        for (int d0 = 0; d0 < 64; d0 += 4) {
            float q0v = Qt[d0][tid],     q1v = Qt[d0 + 1][tid];
            float q2v = Qt[d0 + 2][tid], q3v = Qt[d0 + 3][tid];
            #pragma unroll
            for (int c = 0; c < 32; c++) {
                const float4 kv = *(const float4*)&Ks[c][d0];
                s[c] += q0v * kv.x + q1v * kv.y + q2v * kv.z + q3v * kv.w;
            }
        }

        float mloc = -1e30f;
        #pragma unroll
        for (int c = 0; c < 32; c++) {
            if (k0 + c > qi) s[c] = -1e30f;
            mloc = fmaxf(mloc, s[c]);
        }
        float mn  = fmaxf(m, mloc);
        float fac = exp2f(m - mn);
        l *= fac;
        #pragma unroll
        for (int d = 0; d < 64; d++) O[d] *= fac;
        #pragma unroll
        for (int c = 0; c < 32; c++) {
            float p = exp2f(s[c] - mn);
            l += p;
            #pragma unroll
            for (int d0 = 0; d0 < 64; d0 += 4) {
                const float4 vv = *(const float4*)&Vs[c][d0];
                O[d0]     += p * vv.x;
                O[d0 + 1] += p * vv.y;
                O[d0 + 2] += p * vv.z;
                O[d0 + 3] += p * vv.w;
            }
        }
        m = mn;
    }

    float inv = 1.f / l;
    float* ob = ctx + (size_t)(b * TT + q0 + tid) * EE + h * DD;
    #pragma unroll
    for (int d = 0; d < 64; d++) ob[d] = O[d] * inv;
}

// ============================================================
extern "C" void kernel_launch(void* const* d_in, const int* in_sizes, int n_in,
                              void* d_out, int out_size)
{
    const float* x   = (const float*)d_in[0];
    const float* wq  = (const float*)d_in[1];
    const float* wk  = (const float*)d_in[2];
    const float* wv  = (const float*)d_in[3];
    const float* wo  = (const float*)d_in[4];
    const float* bo  = (const float*)d_in[5];
    const float* l1s = (const float*)d_in[6];
    const float* l1b = (const float*)d_in[7];
    const float* l2s = (const float*)d_in[8];
    const float* l2b = (const float*)d_in[9];
    const float* w1  = (const float*)d_in[10];
    const float* b1  = (const float*)d_in[11];
    const float* w2  = (const float*)d_in[12];
    const float* b2  = (const float*)d_in[13];
    float* out = (float*)d_out;

    float *h1, *qp, *kp, *vp, *ctx, *x1, *h2, *f1;
    cudaGetSymbolAddress((void**)&h1,  g_h1);
    cudaGetSymbolAddress((void**)&qp,  g_q);
    cudaGetSymbolAddress((void**)&kp,  g_k);
    cudaGetSymbolAddress((void**)&vp,  g_v);
    cudaGetSymbolAddress((void**)&ctx, g_ctx);
    cudaGetSymbolAddress((void**)&x1,  g_x1);
    cudaGetSymbolAddress((void**)&h2,  g_h2);
    cudaGetSymbolAddress((void**)&f1,  g_f1);

    // LN1
    ln_kernel<<<MM, 256>>>(x, l1s, l1b, h1);
    // QKV projections
    dim3 gE(EE / 128, MM / 128);          // (6, 32)
    sgemm_kernel<0><<<gE, 256>>>(h1, wq, qp, MM, EE, EE, nullptr, nullptr);
    sgemm_kernel<0><<<gE, 256>>>(h1, wk, kp, MM, EE, EE, nullptr, nullptr);
    sgemm_kernel<0><<<gE, 256>>>(h1, wv, vp, MM, EE, EE, nullptr, nullptr);
    // Attention
    attn_kernel<<<dim3(TT / 128, BB * HH), 128>>>(qp, kp, vp, ctx);
    // Output projection + bias + residual(x)
    sgemm_kernel<1><<<gE, 256>>>(ctx, wo, x1, MM, EE, EE, bo, x);
    // LN2
    ln_kernel<<<MM, 256>>>(x1, l2s, l2b, h2);
    // MLP up + GELU
    dim3 gF(FFN / 128, MM / 128);         // (24, 32)
    sgemm_kernel<2><<<gF, 256>>>(h2, w1, f1, MM, FFN, EE, b1, nullptr);
    // MLP down + bias + residual(x1) -> out
    sgemm_kernel<1><<<gE, 256>>>(f1, w2, out, MM, EE, FFN, b2, x1);
}